// round 10
// baseline (speedup 1.0000x reference)
#include <cuda_runtime.h>
#include <math.h>

#define N_MAX 100000
#define E_MAX 1600000
#define G_NUM 1024
#define SCAN_B 1024
#define NBLK_MAX 128   // ceil(100000/1024)=98

// ---------------- device scratch (no allocation allowed) -------------------
__device__ __align__(16) float g_B0[(long long)N_MAX * 64]; // ping
__device__ __align__(16) float g_B1[(long long)N_MAX * 64]; // pong
__device__ float g_dinv[N_MAX];
__device__ int   g_deg [N_MAX];
__device__ int   g_tmp [N_MAX];        // block-scan partials
__device__ int   g_off [N_MAX + 1];    // CSR offsets (by dst)
__device__ int   g_bsum[NBLK_MAX];     // block sums for scan
__device__ int   g_pos [E_MAX];        // per-edge rank within dst bucket
__device__ int   g_csrc[E_MAX];        // CSR src ids
__device__ float g_pool[G_NUM * 64];

__device__ __forceinline__ float* buf(int s) { return s == 0 ? g_B0 : g_B1; }

// ---------------------------- prep -----------------------------------------
__global__ void k_zero(int n) {
    int i = blockIdx.x * blockDim.x + threadIdx.x;
    if (i < n)          g_deg[i]  = 0;
    if (i < G_NUM * 64) g_pool[i] = 0.f;
}

// pass A: count degree AND record each edge's rank within its dst bucket
__global__ void k_pos(const int* __restrict__ ei, int E) {
    int e = blockIdx.x * blockDim.x + threadIdx.x;
    if (e >= E) return;
    int d = ei[E + e];
    g_pos[e] = atomicAdd(&g_deg[d], 1);
}

// ------------------------- 3-kernel exclusive scan --------------------------
__global__ void k_scan1(int n) {
    __shared__ int s[SCAN_B];
    int t = threadIdx.x;
    int i = blockIdx.x * SCAN_B + t;
    int v = (i < n) ? g_deg[i] : 0;
    s[t] = v;
    __syncthreads();
#pragma unroll
    for (int d = 1; d < SCAN_B; d <<= 1) {
        int x = (t >= d) ? s[t - d] : 0;
        __syncthreads();
        s[t] += x;
        __syncthreads();
    }
    if (i < n) g_tmp[i] = s[t];                 // inclusive
    if (t == SCAN_B - 1) g_bsum[blockIdx.x] = s[t];
}

__global__ void k_scan2(int nblk) {
    __shared__ int s[NBLK_MAX];
    int t = threadIdx.x;
    int v = (t < nblk) ? g_bsum[t] : 0;
    s[t] = v;
    __syncthreads();
#pragma unroll
    for (int d = 1; d < NBLK_MAX; d <<= 1) {
        int x = (t >= d) ? s[t - d] : 0;
        __syncthreads();
        s[t] += x;
        __syncthreads();
    }
    if (t < nblk) g_bsum[t] = s[t] - v;         // exclusive
}

__global__ void k_scan3(int n, int E) {
    int i = blockIdx.x * blockDim.x + threadIdx.x;
    if (i < n) {
        int deg = g_deg[i];
        g_off[i] = g_tmp[i] - deg + g_bsum[i / SCAN_B];  // exclusive
        g_dinv[i] = rsqrtf((float)(deg + 1));            // +1 self loop
    }
    if (i == 0) g_off[n] = E;
}

// pass B: atomic-free placement
__global__ void k_place(const int* __restrict__ ei, int E) {
    int e = blockIdx.x * blockDim.x + threadIdx.x;
    if (e >= E) return;
    int s = ei[e];
    int d = ei[E + e];
    g_csrc[g_off[d] + g_pos[e]] = s;
}

// -------- layer-1 transform: q0 = (x @ W1) * dinv  (thread per node) -------
__global__ void k_transform1(const float* __restrict__ x,
                             const float* __restrict__ W, int n)
{
    __shared__ float sW[128 * 16];
    for (int i = threadIdx.x; i < 128 * 16; i += blockDim.x) sW[i] = W[i];
    __syncthreads();

    int node = blockIdx.x * blockDim.x + threadIdx.x;
    if (node >= n) return;

    const float4* row4 = reinterpret_cast<const float4*>(x) + (long long)node * 32;
    float acc[16];
#pragma unroll
    for (int j = 0; j < 16; j++) acc[j] = 0.f;

    for (int k4 = 0; k4 < 32; k4++) {
        float4 v4 = row4[k4];
        float vv[4] = {v4.x, v4.y, v4.z, v4.w};
#pragma unroll
        for (int u = 0; u < 4; u++) {
            int k = k4 * 4 + u;
#pragma unroll
            for (int j = 0; j < 16; j++)
                acc[j] = fmaf(vv[u], sW[k * 16 + j], acc[j]);
        }
    }

    float di = g_dinv[node];
    float4* out4 = reinterpret_cast<float4*>(g_B0) + (long long)node * 4;
#pragma unroll
    for (int j4 = 0; j4 < 4; j4++)
        out4[j4] = make_float4(acc[j4*4+0]*di, acc[j4*4+1]*di,
                               acc[j4*4+2]*di, acc[j4*4+3]*di);
}

// -------- layer-1 gather: q1 = relu(dinv*(q0+Σq0) + b1) * dinv  ------------
// warp per node, F=16: 8 edge slots x 4 float4-lanes
__global__ void k_gather1(const float* __restrict__ b1, int n)
{
    int node = blockIdx.x * blockDim.y + threadIdx.y;
    if (node >= n) return;
    int lane = threadIdx.x;
    int slot = lane >> 2;
    int f4   = lane & 3;

    const float4* In4 = reinterpret_cast<const float4*>(g_B0);
    int e0 = g_off[node];
    int e1 = g_off[node + 1];

    float4 a = make_float4(0.f, 0.f, 0.f, 0.f);
    if (slot == 0) a = In4[(long long)node * 4 + f4];   // self loop

    for (int e = e0 + slot; e < e1; e += 8) {
        int s = g_csrc[e];
        float4 v = In4[(long long)s * 4 + f4];
        a.x += v.x; a.y += v.y; a.z += v.z; a.w += v.w;
    }
#pragma unroll
    for (int off = 16; off >= 4; off >>= 1) {
        a.x += __shfl_xor_sync(0xffffffffu, a.x, off);
        a.y += __shfl_xor_sync(0xffffffffu, a.y, off);
        a.z += __shfl_xor_sync(0xffffffffu, a.z, off);
        a.w += __shfl_xor_sync(0xffffffffu, a.w, off);
    }
    if (slot == 0) {
        float di = g_dinv[node];
        const float4 b4 = reinterpret_cast<const float4*>(b1)[f4];
        float4 o;
        o.x = fmaxf(a.x * di + b4.x, 0.f) * di;
        o.y = fmaxf(a.y * di + b4.y, 0.f) * di;
        o.z = fmaxf(a.z * di + b4.z, 0.f) * di;
        o.w = fmaxf(a.w * di + b4.w, 0.f) * di;
        reinterpret_cast<float4*>(g_B1)[(long long)node * 4 + f4] = o;
    }
}

// -------- fused layer 2: q2 = relu( (dinv*(q1+Σq1)) @ W2 + b2 ) * dinv -----
// warp per node: gather F=16 (8 slots x 4 lanes) -> butterfly -> 32-lane matmul
__global__ void k_gt2(const float* __restrict__ W, const float* __restrict__ bias, int n)
{
    __shared__ float sW[16 * 32];
    __shared__ float sB[32];
    int tid = threadIdx.y * 32 + threadIdx.x;
    for (int i = tid; i < 16 * 32; i += 256) sW[i] = W[i];
    if (tid < 32) sB[tid] = bias[tid];
    __syncthreads();

    int node = blockIdx.x * blockDim.y + threadIdx.y;
    if (node >= n) return;
    int lane = threadIdx.x;
    int slot = lane >> 2;
    int f4   = lane & 3;

    const float4* In4 = reinterpret_cast<const float4*>(g_B1);
    int e0 = g_off[node];
    int e1 = g_off[node + 1];

    float4 a = make_float4(0.f, 0.f, 0.f, 0.f);
    if (slot == 0) a = In4[(long long)node * 4 + f4];

    for (int e = e0 + slot; e < e1; e += 8) {
        int s = g_csrc[e];
        float4 v = In4[(long long)s * 4 + f4];
        a.x += v.x; a.y += v.y; a.z += v.z; a.w += v.w;
    }
#pragma unroll
    for (int off = 16; off >= 4; off >>= 1) {
        a.x += __shfl_xor_sync(0xffffffffu, a.x, off);
        a.y += __shfl_xor_sync(0xffffffffu, a.y, off);
        a.z += __shfl_xor_sync(0xffffffffu, a.z, off);
        a.w += __shfl_xor_sync(0xffffffffu, a.w, off);
    }
    float di = g_dinv[node];
    a.x *= di; a.y *= di; a.z *= di; a.w *= di;   // m (lanes f4=q hold m[4q..])

    // matmul: lane j computes out feature j
    float acc = sB[lane];
#pragma unroll
    for (int q = 0; q < 4; q++) {
        float mx = __shfl_sync(0xffffffffu, a.x, q);
        float my = __shfl_sync(0xffffffffu, a.y, q);
        float mz = __shfl_sync(0xffffffffu, a.z, q);
        float mw = __shfl_sync(0xffffffffu, a.w, q);
        acc = fmaf(mx, sW[(4*q+0)*32 + lane], acc);
        acc = fmaf(my, sW[(4*q+1)*32 + lane], acc);
        acc = fmaf(mz, sW[(4*q+2)*32 + lane], acc);
        acc = fmaf(mw, sW[(4*q+3)*32 + lane], acc);
    }
    g_B0[(long long)node * 32 + lane] = fmaxf(acc, 0.f) * di;  // pre-scaled
}

// -------- fused layer 3: h3 = relu( (dinv*(q2+Σq2)) @ W3 + b3 )  -----------
// warp per node: gather F=32 (4 slots x 8 lanes) -> butterfly -> 2 outs/lane
__global__ void k_gt3(const float* __restrict__ W, const float* __restrict__ bias, int n)
{
    __shared__ float sW[32 * 64];
    __shared__ float sB[64];
    int tid = threadIdx.y * 32 + threadIdx.x;
    for (int i = tid; i < 32 * 64; i += 256) sW[i] = W[i];
    if (tid < 64) sB[tid] = bias[tid];
    __syncthreads();

    int node = blockIdx.x * blockDim.y + threadIdx.y;
    if (node >= n) return;
    int lane = threadIdx.x;
    int slot = lane >> 3;
    int f4   = lane & 7;

    const float4* In4 = reinterpret_cast<const float4*>(g_B0);
    int e0 = g_off[node];
    int e1 = g_off[node + 1];

    float4 a = make_float4(0.f, 0.f, 0.f, 0.f);
    if (slot == 0) a = In4[(long long)node * 8 + f4];

    for (int e = e0 + slot; e < e1; e += 4) {
        int s = g_csrc[e];
        float4 v = In4[(long long)s * 8 + f4];
        a.x += v.x; a.y += v.y; a.z += v.z; a.w += v.w;
    }
#pragma unroll
    for (int off = 16; off >= 8; off >>= 1) {
        a.x += __shfl_xor_sync(0xffffffffu, a.x, off);
        a.y += __shfl_xor_sync(0xffffffffu, a.y, off);
        a.z += __shfl_xor_sync(0xffffffffu, a.z, off);
        a.w += __shfl_xor_sync(0xffffffffu, a.w, off);
    }
    float di = g_dinv[node];
    a.x *= di; a.y *= di; a.z *= di; a.w *= di;   // m (lanes f4=q hold m[4q..])

    float acc0 = sB[lane];
    float acc1 = sB[lane + 32];
#pragma unroll
    for (int q = 0; q < 8; q++) {
        float mx = __shfl_sync(0xffffffffu, a.x, q);
        float my = __shfl_sync(0xffffffffu, a.y, q);
        float mz = __shfl_sync(0xffffffffu, a.z, q);
        float mw = __shfl_sync(0xffffffffu, a.w, q);
        acc0 = fmaf(mx, sW[(4*q+0)*64 + lane], acc0);
        acc1 = fmaf(mx, sW[(4*q+0)*64 + 32 + lane], acc1);
        acc0 = fmaf(my, sW[(4*q+1)*64 + lane], acc0);
        acc1 = fmaf(my, sW[(4*q+1)*64 + 32 + lane], acc1);
        acc0 = fmaf(mz, sW[(4*q+2)*64 + lane], acc0);
        acc1 = fmaf(mz, sW[(4*q+2)*64 + 32 + lane], acc1);
        acc0 = fmaf(mw, sW[(4*q+3)*64 + lane], acc0);
        acc1 = fmaf(mw, sW[(4*q+3)*64 + 32 + lane], acc1);
    }
    g_B1[(long long)node * 64 + lane]      = fmaxf(acc0, 0.f);
    g_B1[(long long)node * 64 + 32 + lane] = fmaxf(acc1, 0.f);
}

// ----------------- pool: segment max over sorted batch ids -----------------
__global__ void k_pool(const int* __restrict__ batch, int n)
{
    int f = threadIdx.x;                              // 0..63
    int chunk = blockIdx.x * blockDim.y + threadIdx.y;
    int n0 = chunk * 16;
    if (n0 >= n) return;
    int n1 = min(n0 + 16, n);

    int curg = batch[n0];
    float m = g_B1[(long long)n0 * 64 + f];
    for (int i = n0 + 1; i < n1; i++) {
        int g = batch[i];
        float v = g_B1[(long long)i * 64 + f];
        if (g != curg) {
            atomicMax((unsigned int*)&g_pool[curg * 64 + f], __float_as_uint(m));
            curg = g;
            m = v;
        } else {
            m = fmaxf(m, v);
        }
    }
    atomicMax((unsigned int*)&g_pool[curg * 64 + f], __float_as_uint(m));
}

// -------------------- fused MLP head (block per graph) ---------------------
__global__ void k_mlp(const float* __restrict__ W1, const float* __restrict__ b1,
                      const float* __restrict__ W2, const float* __restrict__ b2,
                      float* __restrict__ out)
{
    __shared__ float sp[64];
    __shared__ float sz[256];
    int g = blockIdx.x, j = threadIdx.x;   // 256 threads
    if (j < 64) sp[j] = g_pool[g * 64 + j];
    __syncthreads();
    float acc = b1[j];
#pragma unroll
    for (int k = 0; k < 64; k++) acc = fmaf(sp[k], W1[k * 256 + j], acc);
    sz[j] = fmaxf(acc, 0.f);
    __syncthreads();
    float acc2 = b2[j];
#pragma unroll 8
    for (int k = 0; k < 256; k++) acc2 = fmaf(sz[k], W2[k * 256 + j], acc2);
    out[g * 256 + j] = 1.f / (1.f + expf(-acc2));
}

// ------------------------------ launch -------------------------------------
extern "C" void kernel_launch(void* const* d_in, const int* in_sizes, int n_in,
                              void* d_out, int out_size)
{
    const float* x     = (const float*)d_in[0];
    const int*   ei    = (const int*)d_in[1];    // int32 (JAX x64 disabled)
    const int*   batch = (const int*)d_in[2];
    const float* W1 = (const float*)d_in[3];
    const float* b1 = (const float*)d_in[4];
    const float* W2 = (const float*)d_in[5];
    const float* b2 = (const float*)d_in[6];
    const float* W3 = (const float*)d_in[7];
    const float* b3 = (const float*)d_in[8];
    const float* L1w = (const float*)d_in[9];
    const float* L1b = (const float*)d_in[10];
    const float* L2w = (const float*)d_in[11];
    const float* L2b = (const float*)d_in[12];
    float* out = (float*)d_out;

    int N = in_sizes[0] / 128;
    int E = in_sizes[1] / 2;
    int nblk = (N + SCAN_B - 1) / SCAN_B;

    // CSR build (by destination), rank-then-place (pass B atomic-free)
    k_zero  <<<(N + 255) / 256, 256>>>(N);
    k_pos   <<<(E + 255) / 256, 256>>>(ei, E);
    k_scan1 <<<nblk, SCAN_B>>>(N);
    k_scan2 <<<1, NBLK_MAX>>>(nblk);
    k_scan3 <<<(N + 255) / 256, 256>>>(N, E);
    k_place <<<(E + 255) / 256, 256>>>(ei, E);

    dim3 gb(32, 8);
    int ggrid = (N + 7) / 8;

    k_transform1<<<(N + 127) / 128, 128>>>(x, W1, N);  // x -> q0 (B0)
    k_gather1<<<ggrid, gb>>>(b1, N);                   // q0 -> q1 (B1)
    k_gt2    <<<ggrid, gb>>>(W2, b2, N);               // q1 -> q2 (B0)
    k_gt3    <<<ggrid, gb>>>(W3, b3, N);               // q2 -> h3 (B1)

    { dim3 pb(64, 4); int chunks = (N + 15) / 16;
      k_pool<<<(chunks + 3) / 4, pb>>>(batch, N); }
    k_mlp<<<G_NUM, 256>>>(L1w, L1b, L2w, L2b, out);
}